// round 1
// baseline (speedup 1.0000x reference)
#include <cuda_runtime.h>
#include <math.h>

#define TPB 256
#define S_REAL 35
#define S_PAD 40
#define DM 64
#define STATE 24
#define MEMN 10

// smem layout (float offsets)
#define WT_F   0        // 8192 floats (32KB) weight tile, k4-major float4
#define HTS_F  8192     // 5120 floats (40x128) : FF hidden tile / attn-out / head scratch
#define QKV_F  13312    // 7680 floats (40x192)
#define XS_F   20992    // 2560 floats (40x64)
#define YS_F   23552    // 2560 floats (40x64)
#define RED_F  26112    // 8 floats
#define SMEM_FLOATS 26120
#define SMEM_BYTES (SMEM_FLOATS * 4)

static __device__ float g_base[STATE * DM];

__device__ __forceinline__ unsigned long long ffma2(double a, double b, unsigned long long c) {
    unsigned long long r;
    asm("fma.rn.f32x2 %0, %1, %2, %3;"
        : "=l"(r)
        : "l"(__double_as_longlong(a)), "l"(__double_as_longlong(b)), "l"(c));
    return r;
}

__device__ __forceinline__ float unpack_sum(unsigned long long a) {
    float lo = __uint_as_float((unsigned)(a & 0xFFFFFFFFull));
    float hi = __uint_as_float((unsigned)(a >> 32));
    return lo + hi;
}

__device__ __forceinline__ float gelu_f(float x) {
    return 0.5f * x * (1.0f + erff(x * 0.7071067811865475f));
}

// Load weight tile into smem as wt[k4][n] (float4 per entry), so that in the GEMM
// inner loop lanes read consecutive 16B (conflict-free) while x rows broadcast.
template<int K4C>
__device__ __forceinline__ void load_wt(float4* wt, const float4* Wf4, int nrows,
                                        int rowStrideF4, int k4off, int tid) {
    int tot = nrows * K4C;
    for (int idx = tid; idx < tot; idx += TPB) {
        int n = idx / K4C;
        int k4 = idx - n * K4C;
        wt[k4 * nrows + n] = Wf4[n * rowStrideF4 + k4off + k4];
    }
}

// out[s][ooff+n] (+)= act( bias[n] + sum_k x[s][k] * W[n][k] )
// x: smem [40][K4*4] floats (row-contiguous). wt: smem [K4][NT] float4.
// thread (ty,tx): rows s = ty*5..ty*5+4, cols n = tx + c*32 (c < NC).
template<int NC, int K4, int NT, bool GELUA, bool ACC>
__device__ __forceinline__ void gemm_tile(const float* xsrc, const float* wtf,
                                          float* out, int ostride, int ooff,
                                          const float* bias, int tx, int ty) {
    const double2* x2 = reinterpret_cast<const double2*>(xsrc);
    const double2* wt = reinterpret_cast<const double2*>(wtf);
    unsigned long long acc[5][NC];
#pragma unroll
    for (int r = 0; r < 5; r++)
#pragma unroll
        for (int c = 0; c < NC; c++) acc[r][c] = 0ull;

    const int s0 = ty * 5;
#pragma unroll
    for (int k4 = 0; k4 < K4; k4++) {
        double2 xr[5];
#pragma unroll
        for (int r = 0; r < 5; r++) xr[r] = x2[(s0 + r) * K4 + k4];  // warp broadcast
#pragma unroll
        for (int c = 0; c < NC; c++) {
            double2 w = wt[k4 * NT + tx + c * 32];  // lanes consecutive 16B
#pragma unroll
            for (int r = 0; r < 5; r++) {
                acc[r][c] = ffma2(xr[r].x, w.x, acc[r][c]);
                acc[r][c] = ffma2(xr[r].y, w.y, acc[r][c]);
            }
        }
    }
#pragma unroll
    for (int r = 0; r < 5; r++) {
#pragma unroll
        for (int c = 0; c < NC; c++) {
            int n = tx + c * 32;
            float v = unpack_sum(acc[r][c]);
            if (bias) v += bias[n];
            if (GELUA) v = gelu_f(v);
            int oi = (s0 + r) * ostride + ooff + n;
            if (ACC) out[oi] += v; else out[oi] = v;
        }
    }
}

__device__ __forceinline__ void attention(const float* qkvs, float* ao, int tid) {
    const float scale = 0.35355339059327373f;  // 1/sqrt(8)
    for (int pair = tid; pair < 8 * S_REAL; pair += TPB) {
        int i = pair % S_REAL;
        int h = pair / S_REAL;
        const float* qp = qkvs + i * 192 + h * 8;
        float q[8];
#pragma unroll
        for (int d = 0; d < 8; d++) q[d] = qp[d];
        float sc[S_REAL];
        float mx = -1e30f;
#pragma unroll
        for (int j = 0; j < S_REAL; j++) {
            const float* kp = qkvs + j * 192 + 64 + h * 8;
            float a = 0.f;
#pragma unroll
            for (int d = 0; d < 8; d++) a += q[d] * kp[d];
            a *= scale;
            sc[j] = a;
            mx = fmaxf(mx, a);
        }
        float sum = 0.f;
#pragma unroll
        for (int j = 0; j < S_REAL; j++) { float e = __expf(sc[j] - mx); sc[j] = e; sum += e; }
        float inv = 1.f / sum;
#pragma unroll
        for (int d = 0; d < 8; d++) {
            float o = 0.f;
#pragma unroll
            for (int j = 0; j < S_REAL; j++) o += sc[j] * qkvs[j * 192 + 128 + h * 8 + d];
            ao[i * 64 + h * 8 + d] = o * inv;
        }
    }
}

__device__ __forceinline__ void layernorm(const float* src, float* dst,
                                          const float* g, const float* b, int tid) {
    int w = tid >> 5, lane = tid & 31;
    float g0 = g[lane], g1 = g[lane + 32], b0 = b[lane], b1 = b[lane + 32];
    for (int row = w; row < S_REAL; row += 8) {
        float v0 = src[row * 64 + lane], v1 = src[row * 64 + lane + 32];
        float s = v0 + v1, q = v0 * v0 + v1 * v1;
#pragma unroll
        for (int off = 16; off; off >>= 1) {
            s += __shfl_xor_sync(0xffffffffu, s, off);
            q += __shfl_xor_sync(0xffffffffu, q, off);
        }
        float m = s * (1.f / 64.f);
        float var = q * (1.f / 64.f) - m * m;
        float rs = rsqrtf(var + 1e-5f);
        dst[row * 64 + lane]      = (v0 - m) * rs * g0 + b0;
        dst[row * 64 + lane + 32] = (v1 - m) * rs * g1 + b1;
    }
}

// batch-independent: mean token embedding + positional + (trait_b + intent_b)
__global__ void base_kernel(const int* __restrict__ toks, const float* __restrict__ temb,
                            const float* __restrict__ demb, const float* __restrict__ trait_b,
                            const float* __restrict__ intent_b) {
    int i = blockIdx.x;
    int d = threadIdx.x;
    float s = 0.f;
#pragma unroll
    for (int t = 0; t < 8; t++) s += temb[(size_t)toks[i * 8 + t] * DM + d];
    g_base[i * DM + d] = s * 0.125f + demb[i * DM + d] + trait_b[d] + intent_b[d];
}

__global__ void __launch_bounds__(TPB, 2)
fused_kernel(const float* __restrict__ traits, const float* __restrict__ rel,
             const float* __restrict__ memc, const float* __restrict__ trait_W,
             const float* __restrict__ intent_W, const float* __restrict__ cls,
             const float* __restrict__ Wqkv, const float* __restrict__ bqkv,
             const float* __restrict__ Wo, const float* __restrict__ bo,
             const float* __restrict__ ln1g, const float* __restrict__ ln1b,
             const float* __restrict__ W1, const float* __restrict__ b1,
             const float* __restrict__ W2, const float* __restrict__ b2,
             const float* __restrict__ ln2g, const float* __restrict__ ln2b,
             const float* __restrict__ outW, const float* __restrict__ outb,
             const float* __restrict__ outlng, const float* __restrict__ outlnb,
             float* __restrict__ out_sit, float* __restrict__ out_seq,
             float* __restrict__ out_mem) {
    extern __shared__ float smem[];
    float* wtf  = smem + WT_F;
    float4* wt4 = reinterpret_cast<float4*>(wtf);
    float* hts  = smem + HTS_F;
    float* qkvs = smem + QKV_F;
    float* xs   = smem + XS_F;
    float* ys   = smem + YS_F;
    float* red  = smem + RED_F;

    const int tid = threadIdx.x;
    const int tx = tid & 31, ty = tid >> 5;
    const int b = blockIdx.x;

    // ---- build x[40][64] (rows >= 35 zero) ----
    for (int idx = tid; idx < S_PAD * DM; idx += TPB) {
        int s = idx >> 6, d = idx & 63;
        float v = 0.f;
        if (s == 0) {
            v = cls[d];
        } else if (s <= STATE) {
            int i = s - 1;
            float t0 = traits[(b * STATE + i) * 2];
            float t1 = traits[(b * STATE + i) * 2 + 1];
            v = g_base[i * DM + d] + t0 * trait_W[d * 2] + t1 * trait_W[d * 2 + 1]
                + rel[b * STATE + i] * intent_W[d];
        } else if (s < S_REAL) {
            v = memc[((size_t)b * MEMN + (s - 25)) * DM + d];
        }
        xs[idx] = v;
    }
    __syncthreads();

    for (int l = 0; l < 3; l++) {
        const float* Wq = Wqkv + l * 192 * 64;
        // ---- QKV (two 96-wide passes) ----
#pragma unroll
        for (int p = 0; p < 2; p++) {
            load_wt<16>(wt4, (const float4*)(Wq + p * 96 * 64), 96, 16, 0, tid);
            __syncthreads();
            gemm_tile<3, 16, 96, false, false>(xs, wtf, qkvs, 192, p * 96,
                                               bqkv + l * 192 + p * 96, tx, ty);
            __syncthreads();
        }
        // ---- attention -> ao (in hts) ----
        attention(qkvs, hts, tid);
        __syncthreads();
        // ---- y = x + ao @ Wo^T + bo ; x = LN1(y) ----
        load_wt<16>(wt4, (const float4*)(Wo + l * 64 * 64), 64, 16, 0, tid);
        for (int idx = tid; idx < S_PAD * DM; idx += TPB) ys[idx] = xs[idx];
        __syncthreads();
        gemm_tile<2, 16, 64, false, true>(hts, wtf, ys, 64, 0, bo + l * 64, tx, ty);
        __syncthreads();
        layernorm(ys, xs, ln1g + l * 64, ln1b + l * 64, tid);
        __syncthreads();
        // ---- FF: y = x + gelu(x@W1^T+b1)@W2^T+b2 ; x = LN2(y) ----
        for (int idx = tid; idx < S_PAD * DM; idx += TPB) ys[idx] = xs[idx];
        for (int jt = 0; jt < 4; jt++) {
            load_wt<16>(wt4, (const float4*)(W1 + (l * 512 + jt * 128) * 64), 128, 16, 0, tid);
            __syncthreads();
            gemm_tile<4, 16, 128, true, false>(xs, wtf, hts, 128, 0,
                                               b1 + l * 512 + jt * 128, tx, ty);
            __syncthreads();
            load_wt<32>(wt4, (const float4*)(W2 + l * 64 * 512), 64, 128, jt * 32, tid);
            __syncthreads();
            gemm_tile<2, 32, 64, false, true>(hts, wtf, ys, 64, 0,
                                              (jt == 0) ? (b2 + l * 64) : (const float*)nullptr,
                                              tx, ty);
            __syncthreads();
        }
        layernorm(ys, xs, ln2g + l * 64, ln2b + l * 64, tid);
        __syncthreads();
    }

    // ---- situation = LN(x[0] @ outW^T + outb) ----
    if (tid < 128) {
        float a = outb[tid];
        const float* wr = outW + tid * 64;
#pragma unroll
        for (int k = 0; k < 64; k++) a += xs[k] * wr[k];
        hts[tid] = a;
    }
    __syncthreads();
    if (tid < 128) {
        float v = hts[tid];
        float s = v, q = v * v;
#pragma unroll
        for (int off = 16; off; off >>= 1) {
            s += __shfl_xor_sync(0xffffffffu, s, off);
            q += __shfl_xor_sync(0xffffffffu, q, off);
        }
        if ((tid & 31) == 0) { red[tid >> 5] = s; red[4 + (tid >> 5)] = q; }
    }
    __syncthreads();
    if (tid < 128) {
        float S = red[0] + red[1] + red[2] + red[3];
        float Q = red[4] + red[5] + red[6] + red[7];
        float m = S * (1.f / 128.f);
        float var = Q * (1.f / 128.f) - m * m;
        float rs = rsqrtf(var + 1e-5f);
        out_sit[(size_t)b * 128 + tid] = (hts[tid] - m) * rs * outlng[tid] + outlnb[tid];
    }
    // ---- situation_sequence = x rows 1..24 ----
    for (int idx = tid; idx < STATE * DM; idx += TPB)
        out_seq[(size_t)b * STATE * DM + idx] = xs[DM + idx];
    // ---- new_memory = [memory_context rows 1..9, mean(seq rows)] ----
    for (int idx = tid; idx < 9 * DM; idx += TPB)
        out_mem[(size_t)b * MEMN * DM + idx] = memc[(size_t)b * MEMN * DM + DM + idx];
    if (tid < 64) {
        float s = 0.f;
#pragma unroll
        for (int i = 1; i <= STATE; i++) s += xs[i * 64 + tid];
        out_mem[(size_t)b * MEMN * DM + 9 * DM + tid] = s * (1.f / 24.f);
    }
}

extern "C" void kernel_launch(void* const* d_in, const int* in_sizes, int n_in,
                              void* d_out, int out_size) {
    const int*   toks     = (const int*)d_in[0];
    const float* traits   = (const float*)d_in[1];
    const float* rel      = (const float*)d_in[2];
    const float* memc     = (const float*)d_in[3];
    const float* temb     = (const float*)d_in[4];
    const float* demb     = (const float*)d_in[5];
    const float* trait_W  = (const float*)d_in[6];
    const float* trait_b  = (const float*)d_in[7];
    const float* intent_W = (const float*)d_in[8];
    const float* intent_b = (const float*)d_in[9];
    const float* cls      = (const float*)d_in[10];
    const float* Wqkv     = (const float*)d_in[11];
    const float* bqkv     = (const float*)d_in[12];
    const float* Wo       = (const float*)d_in[13];
    const float* bo       = (const float*)d_in[14];
    const float* ln1g     = (const float*)d_in[15];
    const float* ln1b     = (const float*)d_in[16];
    const float* W1       = (const float*)d_in[17];
    const float* b1       = (const float*)d_in[18];
    const float* W2       = (const float*)d_in[19];
    const float* b2       = (const float*)d_in[20];
    const float* outW     = (const float*)d_in[21 + 2];
    const float* outb     = (const float*)d_in[24];
    const float* outlng   = (const float*)d_in[25];
    const float* outlnb   = (const float*)d_in[26];
    const float* ln2g     = (const float*)d_in[21];
    const float* ln2b     = (const float*)d_in[22];

    int B = in_sizes[2] / STATE;  // rel_goal is (B, 24)
    float* out = (float*)d_out;
    float* out_sit = out;
    float* out_seq = out + (size_t)B * 128;
    float* out_mem = out_seq + (size_t)B * STATE * DM;

    base_kernel<<<STATE, DM>>>(toks, temb, demb, trait_b, intent_b);

    cudaFuncSetAttribute(fused_kernel, cudaFuncAttributeMaxDynamicSharedMemorySize, SMEM_BYTES);
    fused_kernel<<<B, TPB, SMEM_BYTES>>>(
        traits, rel, memc, trait_W, intent_W, cls,
        Wqkv, bqkv, Wo, bo, ln1g, ln1b, W1, b1, W2, b2, ln2g, ln2b,
        outW, outb, outlng, outlnb,
        out_sit, out_seq, out_mem);
}

// round 4
// speedup vs baseline: 1.0018x; 1.0018x over previous
#include <cuda_runtime.h>
#include <math.h>

#define TPB 256
#define S_REAL 35
#define S_PAD 40
#define DM 64
#define STATE 24
#define MEMN 10

// smem layout (float offsets)
#define WT_F   0        // 8192 floats (32KB) weight tile, k4-major float4
#define HTS_F  8192     // 5120 floats (40x128) : FF hidden tile / attn-out / head scratch
#define QKV_F  13312    // 7680 floats (40x192)
#define XS_F   20992    // 2560 floats (40x64)
#define YS_F   23552    // 2560 floats (40x64)
#define RED_F  26112    // 8 floats
#define SMEM_FLOATS 26120
#define SMEM_BYTES (SMEM_FLOATS * 4)

static __device__ float g_base[STATE * DM];

__device__ __forceinline__ unsigned long long ffma2(double a, double b, unsigned long long c) {
    unsigned long long r;
    asm("fma.rn.f32x2 %0, %1, %2, %3;"
        : "=l"(r)
        : "l"(__double_as_longlong(a)), "l"(__double_as_longlong(b)), "l"(c));
    return r;
}

__device__ __forceinline__ float unpack_sum(unsigned long long a) {
    float lo = __uint_as_float((unsigned)(a & 0xFFFFFFFFull));
    float hi = __uint_as_float((unsigned)(a >> 32));
    return lo + hi;
}

__device__ __forceinline__ float gelu_f(float x) {
    return 0.5f * x * (1.0f + erff(x * 0.7071067811865475f));
}

// Load weight tile into smem as wt[k4][n] (float4 per entry), so that in the GEMM
// inner loop lanes read consecutive 16B (conflict-free) while x rows broadcast.
template<int K4C>
__device__ __forceinline__ void load_wt(float4* wt, const float4* Wf4, int nrows,
                                        int rowStrideF4, int k4off, int tid) {
    int tot = nrows * K4C;
    for (int idx = tid; idx < tot; idx += TPB) {
        int n = idx / K4C;
        int k4 = idx - n * K4C;
        wt[k4 * nrows + n] = Wf4[n * rowStrideF4 + k4off + k4];
    }
}

// out[s][ooff+n] (+)= act( bias[n] + sum_k x[s][k] * W[n][k] )
// x: smem [40][K4*4] floats (row-contiguous). wt: smem [K4][NT] float4.
// thread (ty,tx): rows s = ty*5..ty*5+4, cols n = tx + c*32 (c < NC).
template<int NC, int K4, int NT, bool GELUA, bool ACC>
__device__ __forceinline__ void gemm_tile(const float* xsrc, const float* wtf,
                                          float* out, int ostride, int ooff,
                                          const float* bias, int tx, int ty) {
    const double2* x2 = reinterpret_cast<const double2*>(xsrc);
    const double2* wt = reinterpret_cast<const double2*>(wtf);
    unsigned long long acc[5][NC];
#pragma unroll
    for (int r = 0; r < 5; r++)
#pragma unroll
        for (int c = 0; c < NC; c++) acc[r][c] = 0ull;

    const int s0 = ty * 5;
#pragma unroll
    for (int k4 = 0; k4 < K4; k4++) {
        double2 xr[5];
#pragma unroll
        for (int r = 0; r < 5; r++) xr[r] = x2[(s0 + r) * K4 + k4];  // warp broadcast
#pragma unroll
        for (int c = 0; c < NC; c++) {
            double2 w = wt[k4 * NT + tx + c * 32];  // lanes consecutive 16B
#pragma unroll
            for (int r = 0; r < 5; r++) {
                acc[r][c] = ffma2(xr[r].x, w.x, acc[r][c]);
                acc[r][c] = ffma2(xr[r].y, w.y, acc[r][c]);
            }
        }
    }
#pragma unroll
    for (int r = 0; r < 5; r++) {
#pragma unroll
        for (int c = 0; c < NC; c++) {
            int n = tx + c * 32;
            float v = unpack_sum(acc[r][c]);
            if (bias) v += bias[n];
            if (GELUA) v = gelu_f(v);
            int oi = (s0 + r) * ostride + ooff + n;
            if (ACC) out[oi] += v; else out[oi] = v;
        }
    }
}

__device__ __forceinline__ void attention(const float* qkvs, float* ao, int tid) {
    const float scale = 0.35355339059327373f;  // 1/sqrt(8)
    for (int pair = tid; pair < 8 * S_REAL; pair += TPB) {
        int i = pair % S_REAL;
        int h = pair / S_REAL;
        const float* qp = qkvs + i * 192 + h * 8;
        float q[8];
#pragma unroll
        for (int d = 0; d < 8; d++) q[d] = qp[d];
        float sc[S_REAL];
        float mx = -1e30f;
#pragma unroll
        for (int j = 0; j < S_REAL; j++) {
            const float* kp = qkvs + j * 192 + 64 + h * 8;
            float a = 0.f;
#pragma unroll
            for (int d = 0; d < 8; d++) a += q[d] * kp[d];
            a *= scale;
            sc[j] = a;
            mx = fmaxf(mx, a);
        }
        float sum = 0.f;
#pragma unroll
        for (int j = 0; j < S_REAL; j++) { float e = __expf(sc[j] - mx); sc[j] = e; sum += e; }
        float inv = 1.f / sum;
#pragma unroll
        for (int d = 0; d < 8; d++) {
            float o = 0.f;
#pragma unroll
            for (int j = 0; j < S_REAL; j++) o += sc[j] * qkvs[j * 192 + 128 + h * 8 + d];
            ao[i * 64 + h * 8 + d] = o * inv;
        }
    }
}

__device__ __forceinline__ void layernorm(const float* src, float* dst,
                                          const float* g, const float* b, int tid) {
    int w = tid >> 5, lane = tid & 31;
    float g0 = g[lane], g1 = g[lane + 32], b0 = b[lane], b1 = b[lane + 32];
    for (int row = w; row < S_REAL; row += 8) {
        float v0 = src[row * 64 + lane], v1 = src[row * 64 + lane + 32];
        float s = v0 + v1, q = v0 * v0 + v1 * v1;
#pragma unroll
        for (int off = 16; off; off >>= 1) {
            s += __shfl_xor_sync(0xffffffffu, s, off);
            q += __shfl_xor_sync(0xffffffffu, q, off);
        }
        float m = s * (1.f / 64.f);
        float var = q * (1.f / 64.f) - m * m;
        float rs = rsqrtf(var + 1e-5f);
        dst[row * 64 + lane]      = (v0 - m) * rs * g0 + b0;
        dst[row * 64 + lane + 32] = (v1 - m) * rs * g1 + b1;
    }
}

// batch-independent: mean token embedding + positional + (trait_b + intent_b)
__global__ void base_kernel(const int* __restrict__ toks, const float* __restrict__ temb,
                            const float* __restrict__ demb, const float* __restrict__ trait_b,
                            const float* __restrict__ intent_b) {
    int i = blockIdx.x;
    int d = threadIdx.x;
    float s = 0.f;
#pragma unroll
    for (int t = 0; t < 8; t++) s += temb[(size_t)toks[i * 8 + t] * DM + d];
    g_base[i * DM + d] = s * 0.125f + demb[i * DM + d] + trait_b[d] + intent_b[d];
}

__global__ void __launch_bounds__(TPB, 2)
fused_kernel(const float* __restrict__ traits, const float* __restrict__ rel,
             const float* __restrict__ memc, const float* __restrict__ trait_W,
             const float* __restrict__ intent_W, const float* __restrict__ cls,
             const float* __restrict__ Wqkv, const float* __restrict__ bqkv,
             const float* __restrict__ Wo, const float* __restrict__ bo,
             const float* __restrict__ ln1g, const float* __restrict__ ln1b,
             const float* __restrict__ W1, const float* __restrict__ b1,
             const float* __restrict__ W2, const float* __restrict__ b2,
             const float* __restrict__ ln2g, const float* __restrict__ ln2b,
             const float* __restrict__ outW, const float* __restrict__ outb,
             const float* __restrict__ outlng, const float* __restrict__ outlnb,
             float* __restrict__ out_sit, float* __restrict__ out_seq,
             float* __restrict__ out_mem) {
    extern __shared__ float smem[];
    float* wtf  = smem + WT_F;
    float4* wt4 = reinterpret_cast<float4*>(wtf);
    float* hts  = smem + HTS_F;
    float* qkvs = smem + QKV_F;
    float* xs   = smem + XS_F;
    float* ys   = smem + YS_F;
    float* red  = smem + RED_F;

    const int tid = threadIdx.x;
    const int tx = tid & 31, ty = tid >> 5;
    const int b = blockIdx.x;

    // ---- build x[40][64] (rows >= 35 zero) ----
    for (int idx = tid; idx < S_PAD * DM; idx += TPB) {
        int s = idx >> 6, d = idx & 63;
        float v = 0.f;
        if (s == 0) {
            v = cls[d];
        } else if (s <= STATE) {
            int i = s - 1;
            float t0 = traits[(b * STATE + i) * 2];
            float t1 = traits[(b * STATE + i) * 2 + 1];
            v = g_base[i * DM + d] + t0 * trait_W[d * 2] + t1 * trait_W[d * 2 + 1]
                + rel[b * STATE + i] * intent_W[d];
        } else if (s < S_REAL) {
            v = memc[((size_t)b * MEMN + (s - 25)) * DM + d];
        }
        xs[idx] = v;
    }
    __syncthreads();

    for (int l = 0; l < 3; l++) {
        const float* Wq = Wqkv + l * 192 * 64;
        // ---- QKV (two 96-wide passes) ----
#pragma unroll
        for (int p = 0; p < 2; p++) {
            load_wt<16>(wt4, (const float4*)(Wq + p * 96 * 64), 96, 16, 0, tid);
            __syncthreads();
            gemm_tile<3, 16, 96, false, false>(xs, wtf, qkvs, 192, p * 96,
                                               bqkv + l * 192 + p * 96, tx, ty);
            __syncthreads();
        }
        // ---- attention -> ao (in hts) ----
        attention(qkvs, hts, tid);
        __syncthreads();
        // ---- y = x + ao @ Wo^T + bo ; x = LN1(y) ----
        load_wt<16>(wt4, (const float4*)(Wo + l * 64 * 64), 64, 16, 0, tid);
        for (int idx = tid; idx < S_PAD * DM; idx += TPB) ys[idx] = xs[idx];
        __syncthreads();
        gemm_tile<2, 16, 64, false, true>(hts, wtf, ys, 64, 0, bo + l * 64, tx, ty);
        __syncthreads();
        layernorm(ys, xs, ln1g + l * 64, ln1b + l * 64, tid);
        __syncthreads();
        // ---- FF: y = x + gelu(x@W1^T+b1)@W2^T+b2 ; x = LN2(y) ----
        for (int idx = tid; idx < S_PAD * DM; idx += TPB) ys[idx] = xs[idx];
        for (int jt = 0; jt < 4; jt++) {
            load_wt<16>(wt4, (const float4*)(W1 + (l * 512 + jt * 128) * 64), 128, 16, 0, tid);
            __syncthreads();
            gemm_tile<4, 16, 128, true, false>(xs, wtf, hts, 128, 0,
                                               b1 + l * 512 + jt * 128, tx, ty);
            __syncthreads();
            load_wt<32>(wt4, (const float4*)(W2 + l * 64 * 512), 64, 128, jt * 32, tid);
            __syncthreads();
            gemm_tile<2, 32, 64, false, true>(hts, wtf, ys, 64, 0,
                                              (jt == 0) ? (b2 + l * 64) : (const float*)nullptr,
                                              tx, ty);
            __syncthreads();
        }
        layernorm(ys, xs, ln2g + l * 64, ln2b + l * 64, tid);
        __syncthreads();
    }

    // ---- situation = LN(x[0] @ outW^T + outb) ----
    if (tid < 128) {
        float a = outb[tid];
        const float* wr = outW + tid * 64;
#pragma unroll
        for (int k = 0; k < 64; k++) a += xs[k] * wr[k];
        hts[tid] = a;
    }
    __syncthreads();
    if (tid < 128) {
        float v = hts[tid];
        float s = v, q = v * v;
#pragma unroll
        for (int off = 16; off; off >>= 1) {
            s += __shfl_xor_sync(0xffffffffu, s, off);
            q += __shfl_xor_sync(0xffffffffu, q, off);
        }
        if ((tid & 31) == 0) { red[tid >> 5] = s; red[4 + (tid >> 5)] = q; }
    }
    __syncthreads();
    if (tid < 128) {
        float S = red[0] + red[1] + red[2] + red[3];
        float Q = red[4] + red[5] + red[6] + red[7];
        float m = S * (1.f / 128.f);
        float var = Q * (1.f / 128.f) - m * m;
        float rs = rsqrtf(var + 1e-5f);
        out_sit[(size_t)b * 128 + tid] = (hts[tid] - m) * rs * outlng[tid] + outlnb[tid];
    }
    // ---- situation_sequence = x rows 1..24 ----
    for (int idx = tid; idx < STATE * DM; idx += TPB)
        out_seq[(size_t)b * STATE * DM + idx] = xs[DM + idx];
    // ---- new_memory = [memory_context rows 1..9, mean(seq rows)] ----
    for (int idx = tid; idx < 9 * DM; idx += TPB)
        out_mem[(size_t)b * MEMN * DM + idx] = memc[(size_t)b * MEMN * DM + DM + idx];
    if (tid < 64) {
        float s = 0.f;
#pragma unroll
        for (int i = 1; i <= STATE; i++) s += xs[i * 64 + tid];
        out_mem[(size_t)b * MEMN * DM + 9 * DM + tid] = s * (1.f / 24.f);
    }
}

extern "C" void kernel_launch(void* const* d_in, const int* in_sizes, int n_in,
                              void* d_out, int out_size) {
    const int*   toks     = (const int*)d_in[0];
    const float* traits   = (const float*)d_in[1];
    const float* rel      = (const float*)d_in[2];
    const float* memc     = (const float*)d_in[3];
    const float* temb     = (const float*)d_in[4];
    const float* demb     = (const float*)d_in[5];
    const float* trait_W  = (const float*)d_in[6];
    const float* trait_b  = (const float*)d_in[7];
    const float* intent_W = (const float*)d_in[8];
    const float* intent_b = (const float*)d_in[9];
    const float* cls      = (const float*)d_in[10];
    const float* Wqkv     = (const float*)d_in[11];
    const float* bqkv     = (const float*)d_in[12];
    const float* Wo       = (const float*)d_in[13];
    const float* bo       = (const float*)d_in[14];
    const float* ln1g     = (const float*)d_in[15];
    const float* ln1b     = (const float*)d_in[16];
    const float* W1       = (const float*)d_in[17];
    const float* b1       = (const float*)d_in[18];
    const float* W2       = (const float*)d_in[19];
    const float* b2       = (const float*)d_in[20];
    const float* outW     = (const float*)d_in[21 + 2];
    const float* outb     = (const float*)d_in[24];
    const float* outlng   = (const float*)d_in[25];
    const float* outlnb   = (const float*)d_in[26];
    const float* ln2g     = (const float*)d_in[21];
    const float* ln2b     = (const float*)d_in[22];

    int B = in_sizes[2] / STATE;  // rel_goal is (B, 24)
    float* out = (float*)d_out;
    float* out_sit = out;
    float* out_seq = out + (size_t)B * 128;
    float* out_mem = out_seq + (size_t)B * STATE * DM;

    base_kernel<<<STATE, DM>>>(toks, temb, demb, trait_b, intent_b);

    cudaFuncSetAttribute(fused_kernel, cudaFuncAttributeMaxDynamicSharedMemorySize, SMEM_BYTES);
    fused_kernel<<<B, TPB, SMEM_BYTES>>>(
        traits, rel, memc, trait_W, intent_W, cls,
        Wqkv, bqkv, Wo, bo, ln1g, ln1b, W1, b1, W2, b2, ln2g, ln2b,
        outW, outb, outlng, outlnb,
        out_sit, out_seq, out_mem);
}